// round 7
// baseline (speedup 1.0000x reference)
#include <cuda_runtime.h>

#define BB 32
#define CC 448
#define HWI 32
#define PIN 1024       // 32*32
#define HWF 64
#define NPOS 4096
#define DP 100
#define DPAD 104
#define OHW 256

// ---- packed f32x2 helpers (sm_103a) ----
__device__ __forceinline__ unsigned long long pack2(float lo, float hi) {
    unsigned long long r;
    asm("mov.b64 %0, {%1, %2};" : "=l"(r) : "f"(lo), "f"(hi));
    return r;
}
__device__ __forceinline__ float2 unpack2(unsigned long long v) {
    float lo, hi;
    asm("mov.b64 {%0, %1}, %2;" : "=f"(lo), "=f"(hi) : "l"(v));
    return make_float2(lo, hi);
}
__device__ __forceinline__ unsigned long long fma2(unsigned long long a,
                                                   unsigned long long b,
                                                   unsigned long long c) {
    unsigned long long d;
    asm("fma.rn.f32x2 %0, %1, %2, %3;" : "=l"(d) : "l"(a), "l"(b), "l"(c));
    return d;
}
__device__ __forceinline__ void mbar_init(unsigned int mbar, unsigned int cnt) {
    asm volatile("mbarrier.init.shared.b64 [%0], %1;" :: "r"(mbar), "r"(cnt) : "memory");
}
__device__ __forceinline__ void mbar_expect_tx(unsigned int mbar, unsigned int bytes) {
    asm volatile("mbarrier.arrive.expect_tx.shared.b64 _, [%0], %1;"
                 :: "r"(mbar), "r"(bytes) : "memory");
}
__device__ __forceinline__ void bulk_g2s(unsigned int sdst, const void* gsrc,
                                         unsigned int bytes, unsigned int mbar) {
    asm volatile("cp.async.bulk.shared::cta.global.mbarrier::complete_tx::bytes "
                 "[%0], [%1], %2, [%3];"
                 :: "r"(sdst), "l"(gsrc), "r"(bytes), "r"(mbar) : "memory");
}
__device__ __forceinline__ void mbar_wait(unsigned int mbar, unsigned int parity) {
    asm volatile(
        "{\n\t.reg .pred P;\n\t"
        "WAIT_%=:\n\t"
        "mbarrier.try_wait.parity.acquire.cta.shared::cta.b64 P, [%0], %1, 0x989680;\n\t"
        "@P bra.uni DONE_%=;\n\t"
        "bra.uni WAIT_%=;\n\t"
        "DONE_%=:\n\t}"
        :: "r"(mbar), "r"(parity) : "memory");
}

// ---- scratch (static device globals; no allocation) ----
__device__ float g_WT[CC * DPAD];          // [c][d], zero-padded d>=100
__device__ float g_meanT[NPOS * DP];       // [n][c]
__device__ float g_proj[(size_t)BB * PIN * DP];  // [b][p][d]  (13.1 MB, fits L2)
__device__ float g_dist[(size_t)BB * NPOS];      // [b][n]

// ---------------------------------------------------------------------------
__global__ void prep_w_kernel(const float* __restrict__ W) {
    int i = blockIdx.x * blockDim.x + threadIdx.x;
    if (i < CC * DPAD) {
        int c = i / DPAD, d = i - c * DPAD;
        g_WT[i] = (d < DP) ? W[d * CC + c] : 0.f;
    }
}

// ---------------------------------------------------------------------------
__global__ void prep_mean_kernel(const float* __restrict__ mean) {
    __shared__ float t[32][33];
    const int n0 = blockIdx.x * 32, c0 = blockIdx.y * 32;
    const int tx = threadIdx.x, ty = threadIdx.y;
#pragma unroll
    for (int j = 0; j < 32; j += 8) {
        int c = c0 + ty + j;
        if (c < DP) t[ty + j][tx] = mean[(size_t)c * NPOS + n0 + tx];
    }
    __syncthreads();
    int c = c0 + tx;
    if (c < DP) {
#pragma unroll
        for (int j = 0; j < 32; j += 8) {
            int n = n0 + ty + j;
            g_meanT[(size_t)n * DP + c] = t[tx][ty + j];
        }
    }
}

// ---------------------------------------------------------------------------
// Projection at 32x32: proj[b][p][d] = sum_c X[b][c][p] * W[d][c] + bias[d]
// Block: 208 threads. Thread = 4p x 8d (f32x2 pairs along d).
// ---------------------------------------------------------------------------
__global__ __launch_bounds__(208) void proj_kernel(const float* __restrict__ X,
                                                   const float* __restrict__ bias) {
    __shared__ float Xs[32][64];     // [c][p]
    __shared__ float Ws[32][DPAD];   // [c][d]
    const int tid = threadIdx.x;
    const int ptile = blockIdx.x;    // 0..15
    const int b = blockIdx.y;        // 0..31
    const int pg = tid & 15;         // p base = pg*4
    const int dg = tid >> 4;         // 0..12
    const int d0 = dg * 8;

    unsigned long long acc[4][4];
#pragma unroll
    for (int k = 0; k < 4; k++)
#pragma unroll
        for (int q = 0; q < 4; q++) acc[k][q] = 0ull;

    const float* Xb = X + ((size_t)b * CC) * PIN + ptile * 64;

    for (int c0 = 0; c0 < CC; c0 += 32) {
        for (int i = tid; i < 32 * 64; i += 208) {
            int c = i >> 6, p = i & 63;
            Xs[c][p] = Xb[(size_t)(c0 + c) * PIN + p];
        }
        for (int i = tid; i < 32 * DPAD; i += 208) {
            int c = i / DPAD, d = i - c * DPAD;
            Ws[c][d] = g_WT[(c0 + c) * DPAD + d];
        }
        __syncthreads();

#pragma unroll 4
        for (int c = 0; c < 32; c++) {
            float4 x0 = *(const float4*)&Xs[c][pg * 4];
            ulonglong2 wa = *(const ulonglong2*)&Ws[c][d0];
            ulonglong2 wb = *(const ulonglong2*)&Ws[c][d0 + 4];
            unsigned long long wp[4] = {wa.x, wa.y, wb.x, wb.y};
            float xv[4] = {x0.x, x0.y, x0.z, x0.w};
            unsigned long long xd[4];
#pragma unroll
            for (int k = 0; k < 4; k++) xd[k] = pack2(xv[k], xv[k]);
#pragma unroll
            for (int k = 0; k < 4; k++)
#pragma unroll
                for (int q = 0; q < 4; q++)
                    acc[k][q] = fma2(xd[k], wp[q], acc[k][q]);
        }
        __syncthreads();
    }

    float4 bi0 = *(const float4*)&bias[d0];
    float4 bi1 = make_float4(0.f, 0.f, 0.f, 0.f);
    if (dg < 12) bi1 = *(const float4*)&bias[d0 + 4];
    const int pbase = ptile * 64 + pg * 4;
#pragma unroll
    for (int k = 0; k < 4; k++) {
        float* o = g_proj + ((size_t)b * PIN + pbase + k) * DP + d0;
        float2 u0 = unpack2(acc[k][0]);
        float2 u1 = unpack2(acc[k][1]);
        *(float4*)o = make_float4(u0.x + bi0.x, u0.y + bi0.y,
                                  u1.x + bi0.z, u1.y + bi0.w);
        if (dg < 12) {
            float2 u2 = unpack2(acc[k][2]);
            float2 u3 = unpack2(acc[k][3]);
            *(float4*)(o + 4) = make_float4(u2.x + bi1.x, u2.y + bi1.y,
                                            u3.x + bi1.z, u3.y + bi1.w);
        }
    }
}

// ---------------------------------------------------------------------------
// Fused 2x bilinear upsample + mean-subtract + Mahalanobis quadratic form.
// One block per n. 256 threads. SINGLE 40 KB cp.async.bulk stages the whole
// IC[n] tile; phase-1 gather overlaps the fill; barrier-free 100-c loop.
// Dynamic smem: DmT[100][36] | IC[10000] | dists[32]
// ---------------------------------------------------------------------------
extern __shared__ float s_maha[];
__global__ __launch_bounds__(256) void maha_kernel(const float* __restrict__ ic) {
    float (*DmT)[36] = (float(*)[36])s_maha;          // 3600 floats
    float* ICs = s_maha + 3600;                       // 10000 floats
    float* dists = s_maha + 13600;                    // 32 floats
    __shared__ __align__(8) unsigned long long mbar_sto;
    const int n = blockIdx.x;
    const int tid = threadIdx.x;

    unsigned int mbar = (unsigned int)__cvta_generic_to_shared(&mbar_sto);
    unsigned int icsh = (unsigned int)__cvta_generic_to_shared(ICs);
    const float* icn = ic + (size_t)n * (DP * DP);

    if (tid == 0) {
        mbar_init(mbar, 1);
        asm volatile("fence.proxy.async.shared::cta;" ::: "memory");
        mbar_expect_tx(mbar, DP * DP * 4);
        bulk_g2s(icsh, icn, DP * DP * 4, mbar);
    }

    // bilinear source taps (half-pixel centers, clamped)
    const int yo = n >> 6, xo = n & 63;
    float yin = (yo + 0.5f) * 0.5f - 0.5f;
    float xin = (xo + 0.5f) * 0.5f - 0.5f;
    int y0 = (int)floorf(yin), x0 = (int)floorf(xin);
    float fy = yin - (float)y0, fx = xin - (float)x0;
    int y0c = max(y0, 0), y1c = min(y0 + 1, HWI - 1);
    int x0c = max(x0, 0), x1c = min(x0 + 1, HWI - 1);
    float w00 = (1.f - fy) * (1.f - fx), w01 = (1.f - fy) * fx;
    float w10 = fy * (1.f - fx),         w11 = fy * fx;
    int p00 = y0c * HWI + x0c, p01 = y0c * HWI + x1c;
    int p10 = y1c * HWI + x0c, p11 = y1c * HWI + x1c;

    // phase 1: DmT[c][b] via float4 taps (overlaps the TMA fill)
    const float* mt = g_meanT + (size_t)n * DP;
    for (int idx = tid; idx < 800; idx += 256) {
        int b = idx / 25;
        int q = idx - b * 25;
        int c = q * 4;
        const float* P = g_proj + (size_t)b * PIN * DP;
        float4 t00 = *(const float4*)&P[p00 * DP + c];
        float4 t01 = *(const float4*)&P[p01 * DP + c];
        float4 t10 = *(const float4*)&P[p10 * DP + c];
        float4 t11 = *(const float4*)&P[p11 * DP + c];
        float4 m4 = *(const float4*)&mt[c];
        DmT[c + 0][b] = w00 * t00.x + w01 * t01.x + w10 * t10.x + w11 * t11.x - m4.x;
        DmT[c + 1][b] = w00 * t00.y + w01 * t01.y + w10 * t10.y + w11 * t11.y - m4.y;
        DmT[c + 2][b] = w00 * t00.z + w01 * t01.z + w10 * t10.z + w11 * t11.z - m4.z;
        DmT[c + 3][b] = w00 * t00.w + w01 * t01.w + w10 * t10.w + w11 * t11.w - m4.w;
    }
    if (tid < BB) dists[tid] = 0.f;
    __syncthreads();
    mbar_wait(mbar, 0);

    const int bg = (tid & 7) * 4;        // batch base (0..28 step 4)
    const int d0 = (tid >> 3) * 4;       // d base (0..96)
    const bool active = tid < 200;

    unsigned long long acc[2][4];        // [b-pair j][d-component q]
#pragma unroll
    for (int j = 0; j < 2; j++)
#pragma unroll
        for (int q = 0; q < 4; q++) acc[j][q] = 0ull;

    if (active) {
        const float* icc = ICs + d0;
#pragma unroll 5
        for (int c = 0; c < DP; c++) {
            float4 icv = *(const float4*)(icc + c * DP);
            unsigned long long icd[4];
            icd[0] = pack2(icv.x, icv.x);
            icd[1] = pack2(icv.y, icv.y);
            icd[2] = pack2(icv.z, icv.z);
            icd[3] = pack2(icv.w, icv.w);
            ulonglong2 da = *(const ulonglong2*)&DmT[c][bg];
            unsigned long long dm[2] = {da.x, da.y};
#pragma unroll
            for (int j = 0; j < 2; j++)
#pragma unroll
                for (int q = 0; q < 4; q++)
                    acc[j][q] = fma2(dm[j], icd[q], acc[j][q]);
        }
#pragma unroll
        for (int j = 0; j < 2; j++) {
            unsigned long long s2 = 0ull;
#pragma unroll
            for (int q = 0; q < 4; q++) {
                unsigned long long dp =
                    *(const unsigned long long*)&DmT[d0 + q][bg + 2 * j];
                s2 = fma2(acc[j][q], dp, s2);
            }
            float2 s = unpack2(s2);
            atomicAdd(&dists[bg + 2 * j], s.x);
            atomicAdd(&dists[bg + 2 * j + 1], s.y);
        }
    }
    __syncthreads();
    if (tid < BB) g_dist[(size_t)tid * NPOS + n] = dists[tid];
}

// ---------------------------------------------------------------------------
__global__ void upsample_kernel(const float* __restrict__ nmin_p,
                                const float* __restrict__ nmax_p,
                                float* __restrict__ out) {
    const int b = blockIdx.y;
    const int i = blockIdx.x * blockDim.x + threadIdx.x;
    const int yo = i >> 6;
    const int xb = (i & 63) * 4;

    float yin = (yo + 0.5f) * 0.25f - 0.5f;
    int y0 = (int)floorf(yin);
    float fy = yin - (float)y0;
    int y0c = max(y0, 0), y1c = min(y0 + 1, HWF - 1);

    const float* dn = g_dist + (size_t)b * NPOS;
    const float* r0 = dn + y0c * HWF;
    const float* r1 = dn + y1c * HWF;
    float nmin = *nmin_p, nmax = *nmax_p;
    float inv = 1.f / (nmax - nmin + 1e-8f);

    float4 res;
    float* resp = (float*)&res;
#pragma unroll
    for (int k = 0; k < 4; k++) {
        int xo = xb + k;
        float xin = (xo + 0.5f) * 0.25f - 0.5f;
        int x0 = (int)floorf(xin);
        float fx = xin - (float)x0;
        int x0c = max(x0, 0), x1c = min(x0 + 1, HWF - 1);
        float v = (1.f - fy) * ((1.f - fx) * r0[x0c] + fx * r0[x1c])
                + fy * ((1.f - fx) * r1[x0c] + fx * r1[x1c]);
        resp[k] = (v - nmin) * inv;
    }
    *(float4*)&out[(size_t)b * (OHW * OHW) + yo * OHW + xb] = res;
}

// ---------------------------------------------------------------------------
extern "C" void kernel_launch(void* const* d_in, const int* in_sizes, int n_in,
                              void* d_out, int out_size) {
    (void)in_sizes; (void)n_in; (void)out_size;
    const float* combined = (const float*)d_in[0];
    const float* proj_w   = (const float*)d_in[1];
    const float* proj_b   = (const float*)d_in[2];
    const float* mean     = (const float*)d_in[3];
    const float* inv_cov  = (const float*)d_in[4];
    const float* nmin     = (const float*)d_in[5];
    const float* nmax     = (const float*)d_in[6];
    float* out = (float*)d_out;

    static int smem_set = 0;
    if (!smem_set) {
        cudaFuncSetAttribute(maha_kernel,
                             cudaFuncAttributeMaxDynamicSharedMemorySize,
                             13632 * 4);
        smem_set = 1;
    }

    prep_w_kernel<<<(CC * DPAD + 255) / 256, 256>>>(proj_w);
    prep_mean_kernel<<<dim3(NPOS / 32, 4), dim3(32, 8)>>>(mean);
    proj_kernel<<<dim3(16, BB), 208>>>(combined, proj_b);
    maha_kernel<<<NPOS, 256, 13632 * 4>>>(inv_cov);
    upsample_kernel<<<dim3(OHW * OHW / (256 * 4), BB), 256>>>(nmin, nmax, out);
}